// round 5
// baseline (speedup 1.0000x reference)
#include <cuda_runtime.h>
#include <cuda_bf16.h>
#include <cuda_fp16.h>

#define NN 50000
#define NE 800000
#define FF 128
#define NG 128
#define NSCANB ((NN + 255) / 256)   // 196

// ---- device scratch ----
__device__ __align__(16) __half g_hh[NN * FF];   // GEMM output (fp16 payload)
__device__ __align__(16) float g_a[NN * FF];     // aggregated output (fp32)
__device__ int   g_cnt[NN];
__device__ float g_dinv[NN];
__device__ int   g_rowptr[NN + 1];
__device__ int   g_cursor[NN];
__device__ int   g_col[NE];
__device__ __align__(16) float g_wgt[NE];
__device__ int   g_gstart[NG + 1];
__device__ int   g_bsum[NSCANB];
__device__ int   g_boff[NSCANB];
__device__ __align__(16) uint4 g_packW[2][4096];

// ---------------- init ----------------
__global__ void init_kernel() {
    int i = blockIdx.x * blockDim.x + threadIdx.x;
    if (i < NN) g_cnt[i] = 0;
    if (i <= NG) g_gstart[i] = NN;
}

__global__ void count_kernel(const int* __restrict__ ei) {
    int e = blockIdx.x * blockDim.x + threadIdx.x;
    if (e < NE) atomicAdd(&g_cnt[ei[NE + e]], 1);
}

// ---------------- hierarchical scan ----------------
__global__ __launch_bounds__(256) void blockscan_kernel() {
    __shared__ int wsum[8];
    int i = blockIdx.x * 256 + threadIdx.x;
    int lane = threadIdx.x & 31, wid = threadIdx.x >> 5;
    int v = (i < NN) ? g_cnt[i] : 0;
    if (i < NN) g_dinv[i] = rsqrtf((float)v + 1.0f);
    int s = v;
    #pragma unroll
    for (int off = 1; off < 32; off <<= 1) {
        int t = __shfl_up_sync(0xffffffffu, s, off);
        if (lane >= off) s += t;
    }
    if (lane == 31) wsum[wid] = s;
    __syncthreads();
    if (wid == 0 && lane < 8) {
        int ws = wsum[lane];
        #pragma unroll
        for (int off = 1; off < 8; off <<= 1) {
            int t = __shfl_up_sync(0xffu, ws, off);
            if (lane >= off) ws += t;
        }
        wsum[lane] = ws;
    }
    __syncthreads();
    int wbase = (wid > 0) ? wsum[wid - 1] : 0;
    if (i < NN) g_rowptr[i] = wbase + (s - v);
    if (threadIdx.x == 255) g_bsum[blockIdx.x] = wsum[7];
}

__global__ __launch_bounds__(256) void scansums_kernel() {
    __shared__ int wsum[8];
    int i = threadIdx.x;
    int lane = i & 31, wid = i >> 5;
    int v = (i < NSCANB) ? g_bsum[i] : 0;
    int s = v;
    #pragma unroll
    for (int off = 1; off < 32; off <<= 1) {
        int t = __shfl_up_sync(0xffffffffu, s, off);
        if (lane >= off) s += t;
    }
    if (lane == 31) wsum[wid] = s;
    __syncthreads();
    if (wid == 0 && lane < 8) {
        int ws = wsum[lane];
        #pragma unroll
        for (int off = 1; off < 8; off <<= 1) {
            int t = __shfl_up_sync(0xffu, ws, off);
            if (lane >= off) ws += t;
        }
        wsum[lane] = ws;
    }
    __syncthreads();
    int wbase = (wid > 0) ? wsum[wid - 1] : 0;
    if (i < NSCANB) g_boff[i] = wbase + (s - v);
    if (i == 0) g_rowptr[NN] = NE;
}

__global__ __launch_bounds__(256) void addoff_kernel(const int* __restrict__ batch) {
    int i = blockIdx.x * 256 + threadIdx.x;
    if (i < NN) {
        int r = g_rowptr[i] + g_boff[blockIdx.x];
        g_rowptr[i] = r;
        g_cursor[i] = r;
        atomicMin(&g_gstart[batch[i]], i);
    }
}

__global__ void fill_kernel(const int* __restrict__ ei) {
    int e = blockIdx.x * blockDim.x + threadIdx.x;
    if (e < NE) {
        int src = ei[e], dst = ei[NE + e];
        int pos = atomicAdd(&g_cursor[dst], 1);
        g_col[pos] = src;
        g_wgt[pos] = g_dinv[src] * g_dinv[dst];
    }
}

// ---------------- parallel suffix-min fixup for empty graphs ----------------
__global__ void gfix_kernel() {
    __shared__ int s[NG + 1];
    int t = threadIdx.x;
    if (t <= NG) s[t] = g_gstart[t];
    __syncthreads();
    #pragma unroll
    for (int off = 1; off <= NG; off <<= 1) {
        int v = NN;
        if (t + off <= NG) v = s[t + off];
        __syncthreads();
        if (t <= NG) s[t] = min(s[t], v);
        __syncthreads();
    }
    if (t <= NG) g_gstart[t] = s[t];
}

// ---------------- bf16 split helpers ----------------
__device__ __forceinline__ void bsplit2(float x, float y, unsigned& hi, unsigned& lo) {
    __nv_bfloat162 h = __floats2bfloat162_rn(x, y);
    float rx = x - __bfloat162float(h.x);
    float ry = y - __bfloat162float(h.y);
    __nv_bfloat162 l = __floats2bfloat162_rn(rx, ry);
    hi = *reinterpret_cast<unsigned*>(&h);
    lo = *reinterpret_cast<unsigned*>(&l);
}

// ---------------- W pack ----------------
__global__ __launch_bounds__(256) void pack_kernel(const float* __restrict__ W1,
                                                   const float* __restrict__ W2) {
    int idx = blockIdx.x * 256 + threadIdx.x;
    int which = idx >> 12;
    int t = idx & 4095;
    const float* W = which ? W2 : W1;
    int lane = t & 31, chunk = t >> 5;
    int kc = chunk >> 4, nc = chunk & 15;
    int g = lane >> 2, tg = lane & 3;
    int n = nc * 8 + g, kb = kc * 16;
    float w0 = W[(kb + 2 * tg) * 128 + n];
    float w1 = W[(kb + 2 * tg + 1) * 128 + n];
    float w2 = W[(kb + 2 * tg + 8) * 128 + n];
    float w3 = W[(kb + 2 * tg + 9) * 128 + n];
    unsigned h0, l0, h1, l1;
    bsplit2(w0, w1, h0, l0);
    bsplit2(w2, w3, h1, l1);
    g_packW[which][t] = make_uint4(h0, h1, l0, l1);
}

// ---------------- tensor-core GEMM -> fp16 h ----------------
#define MMA_BF16(c0,c1,c2,c3,a0,a1,a2,a3,b0,b1)                                \
    asm volatile("mma.sync.aligned.m16n8k16.row.col.f32.bf16.bf16.f32 "        \
                 "{%0,%1,%2,%3}, {%4,%5,%6,%7}, {%8,%9}, {%0,%1,%2,%3};"       \
                 : "+f"(c0), "+f"(c1), "+f"(c2), "+f"(c3)                      \
                 : "r"(a0), "r"(a1), "r"(a2), "r"(a3), "r"(b0), "r"(b1))

__global__ __launch_bounds__(256) void gemm_mma_kernel(const float* __restrict__ Ain,
                                                       int use_ga, int wsel) {
    extern __shared__ uint4 sW[];
    const float* __restrict__ A = use_ga ? g_a : Ain;
    int tid = threadIdx.x;
    const uint4* __restrict__ pW = g_packW[wsel];
    #pragma unroll
    for (int i = 0; i < 16; i++) sW[tid + 256 * i] = pW[tid + 256 * i];
    __syncthreads();

    int warp = tid >> 5, lane = tid & 31;
    int g = lane >> 2, tg = lane & 3;
    int row0 = blockIdx.x * 128 + warp * 16;
    int r0 = row0 + g, r1 = row0 + g + 8;
    int r0c = (r0 < NN) ? r0 : 0;
    int r1c = (r1 < NN) ? r1 : 0;

    float acc[16][4];
    #pragma unroll
    for (int nc = 0; nc < 16; nc++)
        #pragma unroll
        for (int j = 0; j < 4; j++) acc[nc][j] = 0.f;

    #pragma unroll
    for (int kc = 0; kc < 8; kc++) {
        const float* Ar0 = A + (size_t)r0c * 128 + kc * 16;
        const float* Ar1 = A + (size_t)r1c * 128 + kc * 16;
        float2 f00 = *(const float2*)(Ar0 + 2 * tg);
        float2 f01 = *(const float2*)(Ar0 + 2 * tg + 8);
        float2 f10 = *(const float2*)(Ar1 + 2 * tg);
        float2 f11 = *(const float2*)(Ar1 + 2 * tg + 8);
        unsigned ah0, al0, ah1, al1, ah2, al2, ah3, al3;
        bsplit2(f00.x, f00.y, ah0, al0);
        bsplit2(f10.x, f10.y, ah1, al1);
        bsplit2(f01.x, f01.y, ah2, al2);
        bsplit2(f11.x, f11.y, ah3, al3);

        const uint4* wrow = sW + kc * 16 * 32 + lane;
        #pragma unroll
        for (int nc = 0; nc < 16; nc++) {
            uint4 w = wrow[nc * 32];
            MMA_BF16(acc[nc][0], acc[nc][1], acc[nc][2], acc[nc][3],
                     ah0, ah1, ah2, ah3, w.x, w.y);
            MMA_BF16(acc[nc][0], acc[nc][1], acc[nc][2], acc[nc][3],
                     ah0, ah1, ah2, ah3, w.z, w.w);
            MMA_BF16(acc[nc][0], acc[nc][1], acc[nc][2], acc[nc][3],
                     al0, al1, al2, al3, w.x, w.y);
        }
    }

    #pragma unroll
    for (int nc = 0; nc < 16; nc++) {
        int col = nc * 8 + 2 * tg;
        __half2 v0 = __floats2half2_rn(acc[nc][0], acc[nc][1]);
        __half2 v1 = __floats2half2_rn(acc[nc][2], acc[nc][3]);
        if (r0 < NN) *(__half2*)(g_hh + (size_t)r0 * 128 + col) = v0;
        if (r1 < NN) *(__half2*)(g_hh + (size_t)r1 * 128 + col) = v1;
    }
}

// ---------------- aggregation: warp per node, fp16 payload ----------------
__device__ __forceinline__ float4 h4tof4(uint2 u) {
    __half2 p0 = *reinterpret_cast<__half2*>(&u.x);
    __half2 p1 = *reinterpret_cast<__half2*>(&u.y);
    float2 f0 = __half22float2(p0);
    float2 f1 = __half22float2(p1);
    return make_float4(f0.x, f0.y, f1.x, f1.y);
}

__global__ void agg_kernel(const float* __restrict__ bias, int relu) {
    int gw = (blockIdx.x * blockDim.x + threadIdx.x) >> 5;
    int lane = threadIdx.x & 31;
    if (gw >= NN) return;
    const uint2* __restrict__ hh = (const uint2*)g_hh;   // 4 halfs/lane, 32/row
    float4 acc = ((const float4*)bias)[lane];
    float di = g_dinv[gw];
    float s = di * di;
    float4 hv = h4tof4(hh[gw * 32 + lane]);
    acc.x += s * hv.x; acc.y += s * hv.y; acc.z += s * hv.z; acc.w += s * hv.w;

    int e = g_rowptr[gw], ee = g_rowptr[gw + 1];
    for (; e + 4 <= ee; e += 4) {
        int c0 = g_col[e], c1 = g_col[e + 1], c2 = g_col[e + 2], c3 = g_col[e + 3];
        float w0 = g_wgt[e], w1 = g_wgt[e + 1], w2 = g_wgt[e + 2], w3 = g_wgt[e + 3];
        float4 v0 = h4tof4(hh[c0 * 32 + lane]);
        float4 v1 = h4tof4(hh[c1 * 32 + lane]);
        float4 v2 = h4tof4(hh[c2 * 32 + lane]);
        float4 v3 = h4tof4(hh[c3 * 32 + lane]);
        acc.x += w0 * v0.x; acc.y += w0 * v0.y; acc.z += w0 * v0.z; acc.w += w0 * v0.w;
        acc.x += w1 * v1.x; acc.y += w1 * v1.y; acc.z += w1 * v1.z; acc.w += w1 * v1.w;
        acc.x += w2 * v2.x; acc.y += w2 * v2.y; acc.z += w2 * v2.z; acc.w += w2 * v2.w;
        acc.x += w3 * v3.x; acc.y += w3 * v3.y; acc.z += w3 * v3.z; acc.w += w3 * v3.w;
    }
    for (; e < ee; e++) {
        int c = g_col[e];
        float w = g_wgt[e];
        float4 v = h4tof4(hh[c * 32 + lane]);
        acc.x += w * v.x; acc.y += w * v.y; acc.z += w * v.z; acc.w += w * v.w;
    }
    if (relu) {
        acc.x = fmaxf(acc.x, 0.f); acc.y = fmaxf(acc.y, 0.f);
        acc.z = fmaxf(acc.z, 0.f); acc.w = fmaxf(acc.w, 0.f);
    }
    ((float4*)g_a)[gw * 32 + lane] = acc;
}

// ---------------- pool ----------------
__global__ void pool_kernel(float* __restrict__ out) {
    int g = blockIdx.x;
    int c = threadIdx.x;
    int sidx = g_gstart[g], eidx = g_gstart[g + 1];
    float acc = 0.f;
    int i = sidx;
    for (; i + 4 <= eidx; i += 4) {
        float t0 = g_a[i * 128 + c];
        float t1 = g_a[(i + 1) * 128 + c];
        float t2 = g_a[(i + 2) * 128 + c];
        float t3 = g_a[(i + 3) * 128 + c];
        acc += (t0 + t1) + (t2 + t3);
    }
    for (; i < eidx; i++) acc += g_a[i * 128 + c];
    out[g * 128 + c] = acc;
}

extern "C" void kernel_launch(void* const* d_in, const int* in_sizes, int n_in,
                              void* d_out, int out_size) {
    const float* x     = (const float*)d_in[0];
    const int*   ei    = (const int*)d_in[1];
    const int*   batch = (const int*)d_in[2];
    const float* W1    = (const float*)d_in[3];
    const float* b1    = (const float*)d_in[4];
    const float* W2    = (const float*)d_in[5];
    const float* b2    = (const float*)d_in[6];
    float* out = (float*)d_out;

    cudaFuncSetAttribute(gemm_mma_kernel, cudaFuncAttributeMaxDynamicSharedMemorySize, 65536);

    // graph prep
    init_kernel<<<(NN + 255) / 256, 256>>>();
    count_kernel<<<(NE + 255) / 256, 256>>>(ei);
    pack_kernel<<<32, 256>>>(W1, W2);
    blockscan_kernel<<<NSCANB, 256>>>();
    scansums_kernel<<<1, 256>>>();
    addoff_kernel<<<NSCANB, 256>>>(batch);
    fill_kernel<<<(NE + 255) / 256, 256>>>(ei);
    gfix_kernel<<<1, 256>>>();

    // layer 1
    gemm_mma_kernel<<<(NN + 127) / 128, 256, 65536>>>(x, 0, 0);
    agg_kernel<<<(NN * 32 + 255) / 256, 256>>>(b1, 1);
    // layer 2
    gemm_mma_kernel<<<(NN + 127) / 128, 256, 65536>>>(nullptr, 1, 1);
    agg_kernel<<<(NN * 32 + 255) / 256, 256>>>(b2, 0);
    // pool
    pool_kernel<<<NG, 128>>>(out);
}

// round 8
// speedup vs baseline: 1.4535x; 1.4535x over previous
#include <cuda_runtime.h>
#include <cuda_bf16.h>
#include <cuda_fp16.h>

#define NN 50000
#define NE 800000
#define FF 128
#define NG 128
#define NSCANB ((NN + 255) / 256)   // 196

// ---- device scratch ----
__device__ __align__(16) __half g_hh[NN * FF];   // GEMM output (fp16 payload)
__device__ __align__(16) float g_a[NN * FF];     // aggregated output (fp32)
__device__ int   g_cnt[NN];
__device__ float g_dinv[NN];
__device__ int   g_rowptr[NN + 1];
__device__ int   g_cursor[NN];
__device__ __align__(16) int2 g_ew[NE];          // {col, weight-as-int}
__device__ int   g_gstart[NG + 1];
__device__ int   g_bsum[NSCANB];
__device__ int   g_boff[NSCANB];
__device__ __align__(16) uint4 g_packW[2][4096];

// ---------------- init ----------------
__global__ void init_kernel() {
    int i = blockIdx.x * blockDim.x + threadIdx.x;
    if (i < NN) g_cnt[i] = 0;
    if (i <= NG) g_gstart[i] = NN;
}

__global__ void count_kernel(const int* __restrict__ ei) {
    int e = blockIdx.x * blockDim.x + threadIdx.x;
    if (e < NE) atomicAdd(&g_cnt[ei[NE + e]], 1);
}

// ---------------- hierarchical scan ----------------
__global__ __launch_bounds__(256) void blockscan_kernel() {
    __shared__ int wsum[8];
    int i = blockIdx.x * 256 + threadIdx.x;
    int lane = threadIdx.x & 31, wid = threadIdx.x >> 5;
    int v = (i < NN) ? g_cnt[i] : 0;
    if (i < NN) g_dinv[i] = rsqrtf((float)v + 1.0f);
    int s = v;
    #pragma unroll
    for (int off = 1; off < 32; off <<= 1) {
        int t = __shfl_up_sync(0xffffffffu, s, off);
        if (lane >= off) s += t;
    }
    if (lane == 31) wsum[wid] = s;
    __syncthreads();
    if (wid == 0 && lane < 8) {
        int ws = wsum[lane];
        #pragma unroll
        for (int off = 1; off < 8; off <<= 1) {
            int t = __shfl_up_sync(0xffu, ws, off);
            if (lane >= off) ws += t;
        }
        wsum[lane] = ws;
    }
    __syncthreads();
    int wbase = (wid > 0) ? wsum[wid - 1] : 0;
    if (i < NN) g_rowptr[i] = wbase + (s - v);
    if (threadIdx.x == 255) g_bsum[blockIdx.x] = wsum[7];
}

__global__ __launch_bounds__(256) void scansums_kernel() {
    __shared__ int wsum[8];
    int i = threadIdx.x;
    int lane = i & 31, wid = i >> 5;
    int v = (i < NSCANB) ? g_bsum[i] : 0;
    int s = v;
    #pragma unroll
    for (int off = 1; off < 32; off <<= 1) {
        int t = __shfl_up_sync(0xffffffffu, s, off);
        if (lane >= off) s += t;
    }
    if (lane == 31) wsum[wid] = s;
    __syncthreads();
    if (wid == 0 && lane < 8) {
        int ws = wsum[lane];
        #pragma unroll
        for (int off = 1; off < 8; off <<= 1) {
            int t = __shfl_up_sync(0xffu, ws, off);
            if (lane >= off) ws += t;
        }
        wsum[lane] = ws;
    }
    __syncthreads();
    int wbase = (wid > 0) ? wsum[wid - 1] : 0;
    if (i < NSCANB) g_boff[i] = wbase + (s - v);
    if (i == 0) g_rowptr[NN] = NE;
}

__global__ __launch_bounds__(256) void addoff_kernel(const int* __restrict__ batch) {
    int i = blockIdx.x * 256 + threadIdx.x;
    if (i < NN) {
        int r = g_rowptr[i] + g_boff[blockIdx.x];
        g_rowptr[i] = r;
        g_cursor[i] = r;
        atomicMin(&g_gstart[batch[i]], i);
    }
}

__global__ void fill_kernel(const int* __restrict__ ei) {
    int e = blockIdx.x * blockDim.x + threadIdx.x;
    if (e < NE) {
        int src = ei[e], dst = ei[NE + e];
        int pos = atomicAdd(&g_cursor[dst], 1);
        float w = g_dinv[src] * g_dinv[dst];
        g_ew[pos] = make_int2(src, __float_as_int(w));
    }
}

// ---------------- parallel suffix-min fixup ----------------
__global__ void gfix_kernel() {
    __shared__ int s[NG + 1];
    int t = threadIdx.x;
    if (t <= NG) s[t] = g_gstart[t];
    __syncthreads();
    #pragma unroll
    for (int off = 1; off <= NG; off <<= 1) {
        int v = NN;
        if (t + off <= NG) v = s[t + off];
        __syncthreads();
        if (t <= NG) s[t] = min(s[t], v);
        __syncthreads();
    }
    if (t <= NG) g_gstart[t] = s[t];
}

// ---------------- bf16 split helpers ----------------
__device__ __forceinline__ void bsplit2(float x, float y, unsigned& hi, unsigned& lo) {
    __nv_bfloat162 h = __floats2bfloat162_rn(x, y);
    float rx = x - __bfloat162float(h.x);
    float ry = y - __bfloat162float(h.y);
    __nv_bfloat162 l = __floats2bfloat162_rn(rx, ry);
    hi = *reinterpret_cast<unsigned*>(&h);
    lo = *reinterpret_cast<unsigned*>(&l);
}

// ---------------- W pack ----------------
__global__ __launch_bounds__(256) void pack_kernel(const float* __restrict__ W1,
                                                   const float* __restrict__ W2) {
    int idx = blockIdx.x * 256 + threadIdx.x;
    int which = idx >> 12;
    int t = idx & 4095;
    const float* W = which ? W2 : W1;
    int lane = t & 31, chunk = t >> 5;
    int kc = chunk >> 4, nc = chunk & 15;
    int g = lane >> 2, tg = lane & 3;
    int n = nc * 8 + g, kb = kc * 16;
    float w0 = W[(kb + 2 * tg) * 128 + n];
    float w1 = W[(kb + 2 * tg + 1) * 128 + n];
    float w2 = W[(kb + 2 * tg + 8) * 128 + n];
    float w3 = W[(kb + 2 * tg + 9) * 128 + n];
    unsigned h0, l0, h1, l1;
    bsplit2(w0, w1, h0, l0);
    bsplit2(w2, w3, h1, l1);
    g_packW[which][t] = make_uint4(h0, h1, l0, l1);
}

// ---------------- tensor-core GEMM -> fp16 h ----------------
#define MMA_BF16(c0,c1,c2,c3,a0,a1,a2,a3,b0,b1)                                \
    asm volatile("mma.sync.aligned.m16n8k16.row.col.f32.bf16.bf16.f32 "        \
                 "{%0,%1,%2,%3}, {%4,%5,%6,%7}, {%8,%9}, {%0,%1,%2,%3};"       \
                 : "+f"(c0), "+f"(c1), "+f"(c2), "+f"(c3)                      \
                 : "r"(a0), "r"(a1), "r"(a2), "r"(a3), "r"(b0), "r"(b1))

__global__ __launch_bounds__(256) void gemm_mma_kernel(const float* __restrict__ Ain,
                                                       int use_ga, int wsel) {
    extern __shared__ uint4 sW[];
    const float* __restrict__ A = use_ga ? g_a : Ain;
    int tid = threadIdx.x;
    const uint4* __restrict__ pW = g_packW[wsel];
    #pragma unroll
    for (int i = 0; i < 16; i++) sW[tid + 256 * i] = pW[tid + 256 * i];
    __syncthreads();

    int warp = tid >> 5, lane = tid & 31;
    int g = lane >> 2, tg = lane & 3;
    int row0 = blockIdx.x * 128 + warp * 16;
    int r0 = row0 + g, r1 = row0 + g + 8;
    int r0c = (r0 < NN) ? r0 : 0;
    int r1c = (r1 < NN) ? r1 : 0;

    float acc[16][4];
    #pragma unroll
    for (int nc = 0; nc < 16; nc++)
        #pragma unroll
        for (int j = 0; j < 4; j++) acc[nc][j] = 0.f;

    #pragma unroll
    for (int kc = 0; kc < 8; kc++) {
        const float* Ar0 = A + (size_t)r0c * 128 + kc * 16;
        const float* Ar1 = A + (size_t)r1c * 128 + kc * 16;
        float2 f00 = *(const float2*)(Ar0 + 2 * tg);
        float2 f01 = *(const float2*)(Ar0 + 2 * tg + 8);
        float2 f10 = *(const float2*)(Ar1 + 2 * tg);
        float2 f11 = *(const float2*)(Ar1 + 2 * tg + 8);
        unsigned ah0, al0, ah1, al1, ah2, al2, ah3, al3;
        bsplit2(f00.x, f00.y, ah0, al0);
        bsplit2(f10.x, f10.y, ah1, al1);
        bsplit2(f01.x, f01.y, ah2, al2);
        bsplit2(f11.x, f11.y, ah3, al3);

        const uint4* wrow = sW + kc * 16 * 32 + lane;
        #pragma unroll
        for (int nc = 0; nc < 16; nc++) {
            uint4 w = wrow[nc * 32];
            MMA_BF16(acc[nc][0], acc[nc][1], acc[nc][2], acc[nc][3],
                     ah0, ah1, ah2, ah3, w.x, w.y);
            MMA_BF16(acc[nc][0], acc[nc][1], acc[nc][2], acc[nc][3],
                     ah0, ah1, ah2, ah3, w.z, w.w);
            MMA_BF16(acc[nc][0], acc[nc][1], acc[nc][2], acc[nc][3],
                     al0, al1, al2, al3, w.x, w.y);
        }
    }

    #pragma unroll
    for (int nc = 0; nc < 16; nc++) {
        int col = nc * 8 + 2 * tg;
        __half2 v0 = __floats2half2_rn(acc[nc][0], acc[nc][1]);
        __half2 v1 = __floats2half2_rn(acc[nc][2], acc[nc][3]);
        if (r0 < NN) *(__half2*)(g_hh + (size_t)r0 * 128 + col) = v0;
        if (r1 < NN) *(__half2*)(g_hh + (size_t)r1 * 128 + col) = v1;
    }
}

// ---------------- register-only fp16x4 -> float4 (no address-of!) ----------------
__device__ __forceinline__ float4 h4tof4(uint2 u) {
    __half2_raw r0, r1;
    r0.x = (unsigned short)(u.x & 0xFFFFu);
    r0.y = (unsigned short)(u.x >> 16);
    r1.x = (unsigned short)(u.y & 0xFFFFu);
    r1.y = (unsigned short)(u.y >> 16);
    float2 f0 = __half22float2(__half2(r0));
    float2 f1 = __half22float2(__half2(r1));
    return make_float4(f0.x, f0.y, f1.x, f1.y);
}

// ---------------- aggregation: warp per node, fp16 payload ----------------
__global__ void agg_kernel(const float* __restrict__ bias, int relu) {
    int gw = (blockIdx.x * blockDim.x + threadIdx.x) >> 5;
    int lane = threadIdx.x & 31;
    if (gw >= NN) return;
    const uint2* __restrict__ hh = (const uint2*)g_hh;
    float4 acc = ((const float4*)bias)[lane];
    float di = g_dinv[gw];
    float s = di * di;
    float4 hv = h4tof4(hh[gw * 32 + lane]);
    acc.x += s * hv.x; acc.y += s * hv.y; acc.z += s * hv.z; acc.w += s * hv.w;

    int e = g_rowptr[gw], ee = g_rowptr[gw + 1];
    for (; e + 4 <= ee; e += 4) {
        int2 ew0 = g_ew[e],     ew1 = g_ew[e + 1];
        int2 ew2 = g_ew[e + 2], ew3 = g_ew[e + 3];
        float w0 = __int_as_float(ew0.y), w1 = __int_as_float(ew1.y);
        float w2 = __int_as_float(ew2.y), w3 = __int_as_float(ew3.y);
        float4 v0 = h4tof4(hh[ew0.x * 32 + lane]);
        float4 v1 = h4tof4(hh[ew1.x * 32 + lane]);
        float4 v2 = h4tof4(hh[ew2.x * 32 + lane]);
        float4 v3 = h4tof4(hh[ew3.x * 32 + lane]);
        acc.x += w0 * v0.x; acc.y += w0 * v0.y; acc.z += w0 * v0.z; acc.w += w0 * v0.w;
        acc.x += w1 * v1.x; acc.y += w1 * v1.y; acc.z += w1 * v1.z; acc.w += w1 * v1.w;
        acc.x += w2 * v2.x; acc.y += w2 * v2.y; acc.z += w2 * v2.z; acc.w += w2 * v2.w;
        acc.x += w3 * v3.x; acc.y += w3 * v3.y; acc.z += w3 * v3.z; acc.w += w3 * v3.w;
    }
    for (; e < ee; e++) {
        int2 ew = g_ew[e];
        float w = __int_as_float(ew.y);
        float4 v = h4tof4(hh[ew.x * 32 + lane]);
        acc.x += w * v.x; acc.y += w * v.y; acc.z += w * v.z; acc.w += w * v.w;
    }
    if (relu) {
        acc.x = fmaxf(acc.x, 0.f); acc.y = fmaxf(acc.y, 0.f);
        acc.z = fmaxf(acc.z, 0.f); acc.w = fmaxf(acc.w, 0.f);
    }
    ((float4*)g_a)[gw * 32 + lane] = acc;
}

// ---------------- pool ----------------
__global__ void pool_kernel(float* __restrict__ out) {
    int g = blockIdx.x;
    int c = threadIdx.x;
    int sidx = g_gstart[g], eidx = g_gstart[g + 1];
    float acc = 0.f;
    int i = sidx;
    for (; i + 4 <= eidx; i += 4) {
        float t0 = g_a[i * 128 + c];
        float t1 = g_a[(i + 1) * 128 + c];
        float t2 = g_a[(i + 2) * 128 + c];
        float t3 = g_a[(i + 3) * 128 + c];
        acc += (t0 + t1) + (t2 + t3);
    }
    for (; i < eidx; i++) acc += g_a[i * 128 + c];
    out[g * 128 + c] = acc;
}

extern "C" void kernel_launch(void* const* d_in, const int* in_sizes, int n_in,
                              void* d_out, int out_size) {
    const float* x     = (const float*)d_in[0];
    const int*   ei    = (const int*)d_in[1];
    const int*   batch = (const int*)d_in[2];
    const float* W1    = (const float*)d_in[3];
    const float* b1    = (const float*)d_in[4];
    const float* W2    = (const float*)d_in[5];
    const float* b2    = (const float*)d_in[6];
    float* out = (float*)d_out;

    cudaFuncSetAttribute(gemm_mma_kernel, cudaFuncAttributeMaxDynamicSharedMemorySize, 65536);

    // graph prep
    init_kernel<<<(NN + 255) / 256, 256>>>();
    count_kernel<<<(NE + 255) / 256, 256>>>(ei);
    pack_kernel<<<32, 256>>>(W1, W2);
    blockscan_kernel<<<NSCANB, 256>>>();
    scansums_kernel<<<1, 256>>>();
    addoff_kernel<<<NSCANB, 256>>>(batch);
    fill_kernel<<<(NE + 255) / 256, 256>>>(ei);
    gfix_kernel<<<1, 256>>>();

    // layer 1
    gemm_mma_kernel<<<(NN + 127) / 128, 256, 65536>>>(x, 0, 0);
    agg_kernel<<<(NN * 32 + 255) / 256, 256>>>(b1, 1);
    // layer 2
    gemm_mma_kernel<<<(NN + 127) / 128, 256, 65536>>>(nullptr, 1, 1);
    agg_kernel<<<(NN * 32 + 255) / 256, 256>>>(b2, 0);
    // pool
    pool_kernel<<<NG, 128>>>(out);
}

// round 11
// speedup vs baseline: 1.4965x; 1.0296x over previous
#include <cuda_runtime.h>
#include <cuda_bf16.h>
#include <cuda_fp16.h>

#define NN 50000
#define NE 800000
#define FF 128
#define NG 128
#define NSCANB ((NN + 255) / 256)   // 196

// ---- device scratch ----
__device__ __align__(16) __half g_hh[NN * FF];
__device__ __align__(16) float g_a[NN * FF];
__device__ int   g_cnt[NN];
__device__ float g_dinv[NN];
__device__ int   g_rowptr[NN + 1];
__device__ int   g_cursor[NN];
__device__ __align__(16) int2 g_ew[NE];
__device__ int   g_gstart[NG + 1];
__device__ unsigned long long g_state[NSCANB];  // {flag:32 | value:32}
__device__ int   g_ticket;
__device__ __align__(16) uint4 g_packW[2][4096];

// ---------------- init ----------------
__global__ void init_kernel() {
    int i = blockIdx.x * blockDim.x + threadIdx.x;
    if (i < NN) g_cnt[i] = 0;
    if (i <= NG) g_gstart[i] = NN;
    if (i < NSCANB) g_state[i] = 0ull;
    if (i == 0) g_ticket = 0;
}

__global__ void count_kernel(const int* __restrict__ ei) {
    int e = blockIdx.x * blockDim.x + threadIdx.x;
    if (e < NE) atomicAdd(&g_cnt[ei[NE + e]], 1);
}

// ---------------- single-pass decoupled-lookback scan ----------------
// Computes exclusive scan of g_cnt -> g_rowptr/g_cursor, plus dinv and gstart.
__global__ __launch_bounds__(256) void scanall_kernel(const int* __restrict__ batch) {
    __shared__ int wsum[8];
    __shared__ int sbid;
    __shared__ int sprev;
    int tid = threadIdx.x, lane = tid & 31, wid = tid >> 5;
    if (tid == 0) sbid = atomicAdd(&g_ticket, 1);
    __syncthreads();
    int b = sbid;
    int i = b * 256 + tid;
    int v = (i < NN) ? g_cnt[i] : 0;
    int s = v;
    #pragma unroll
    for (int off = 1; off < 32; off <<= 1) {
        int t = __shfl_up_sync(0xffffffffu, s, off);
        if (lane >= off) s += t;
    }
    if (lane == 31) wsum[wid] = s;
    __syncthreads();
    if (wid == 0 && lane < 8) {
        int ws = wsum[lane];
        #pragma unroll
        for (int off = 1; off < 8; off <<= 1) {
            int t = __shfl_up_sync(0xffu, ws, off);
            if (lane >= off) ws += t;
        }
        wsum[lane] = ws;
    }
    __syncthreads();
    int total = wsum[7];

    if (tid == 0) {
        if (b == 0) {
            atomicExch(&g_state[0], (2ull << 32) | (unsigned)total);
            sprev = 0;
        } else {
            atomicExch(&g_state[b], (1ull << 32) | (unsigned)total);
            int sum = 0;
            int j = b - 1;
            while (true) {
                unsigned long long st = atomicAdd(&g_state[j], 0ull);
                unsigned f = (unsigned)(st >> 32);
                if (f == 0) continue;
                sum += (int)(unsigned)st;
                if (f == 2u) break;
                j--;
            }
            sprev = sum;
            atomicExch(&g_state[b], (2ull << 32) | (unsigned)(sum + total));
        }
    }
    __syncthreads();
    int base = sprev;
    int wbase = (wid > 0) ? wsum[wid - 1] : 0;
    if (i < NN) {
        int r = base + wbase + (s - v);
        g_rowptr[i] = r;
        g_cursor[i] = r;
        g_dinv[i] = rsqrtf((float)v + 1.0f);
        atomicMin(&g_gstart[batch[i]], i);
    }
    if (i == NN) g_rowptr[NN] = NE;
}

__global__ void fill_kernel(const int* __restrict__ ei) {
    int e = blockIdx.x * blockDim.x + threadIdx.x;
    if (e < NE) {
        int src = ei[e], dst = ei[NE + e];
        int pos = atomicAdd(&g_cursor[dst], 1);
        float w = g_dinv[src] * g_dinv[dst];
        g_ew[pos] = make_int2(src, __float_as_int(w));
    }
}

// ---------------- bf16 split helpers ----------------
__device__ __forceinline__ void bsplit2(float x, float y, unsigned& hi, unsigned& lo) {
    __nv_bfloat162 h = __floats2bfloat162_rn(x, y);
    float rx = x - __bfloat162float(h.x);
    float ry = y - __bfloat162float(h.y);
    __nv_bfloat162 l = __floats2bfloat162_rn(rx, ry);
    hi = *reinterpret_cast<unsigned*>(&h);
    lo = *reinterpret_cast<unsigned*>(&l);
}

// ---------------- W pack ----------------
__global__ __launch_bounds__(256) void pack_kernel(const float* __restrict__ W1,
                                                   const float* __restrict__ W2) {
    int idx = blockIdx.x * 256 + threadIdx.x;
    int which = idx >> 12;
    int t = idx & 4095;
    const float* W = which ? W2 : W1;
    int lane = t & 31, chunk = t >> 5;
    int kc = chunk >> 4, nc = chunk & 15;
    int g = lane >> 2, tg = lane & 3;
    int n = nc * 8 + g, kb = kc * 16;
    float w0 = W[(kb + 2 * tg) * 128 + n];
    float w1 = W[(kb + 2 * tg + 1) * 128 + n];
    float w2 = W[(kb + 2 * tg + 8) * 128 + n];
    float w3 = W[(kb + 2 * tg + 9) * 128 + n];
    unsigned h0, l0, h1, l1;
    bsplit2(w0, w1, h0, l0);
    bsplit2(w2, w3, h1, l1);
    g_packW[which][t] = make_uint4(h0, h1, l0, l1);
}

// ---------------- tensor-core GEMM -> fp16 h ----------------
#define MMA_BF16(c0,c1,c2,c3,a0,a1,a2,a3,b0,b1)                                \
    asm volatile("mma.sync.aligned.m16n8k16.row.col.f32.bf16.bf16.f32 "        \
                 "{%0,%1,%2,%3}, {%4,%5,%6,%7}, {%8,%9}, {%0,%1,%2,%3};"       \
                 : "+f"(c0), "+f"(c1), "+f"(c2), "+f"(c3)                      \
                 : "r"(a0), "r"(a1), "r"(a2), "r"(a3), "r"(b0), "r"(b1))

__global__ __launch_bounds__(256) void gemm_mma_kernel(const float* __restrict__ Ain,
                                                       int use_ga, int wsel) {
    extern __shared__ uint4 sW[];
    const float* __restrict__ A = use_ga ? g_a : Ain;
    int tid = threadIdx.x;
    const uint4* __restrict__ pW = g_packW[wsel];
    #pragma unroll
    for (int i = 0; i < 16; i++) sW[tid + 256 * i] = pW[tid + 256 * i];
    __syncthreads();

    int warp = tid >> 5, lane = tid & 31;
    int g = lane >> 2, tg = lane & 3;
    int row0 = blockIdx.x * 128 + warp * 16;
    int r0 = row0 + g, r1 = row0 + g + 8;
    int r0c = (r0 < NN) ? r0 : 0;
    int r1c = (r1 < NN) ? r1 : 0;

    float acc[16][4];
    #pragma unroll
    for (int nc = 0; nc < 16; nc++)
        #pragma unroll
        for (int j = 0; j < 4; j++) acc[nc][j] = 0.f;

    #pragma unroll
    for (int kc = 0; kc < 8; kc++) {
        const float* Ar0 = A + (size_t)r0c * 128 + kc * 16;
        const float* Ar1 = A + (size_t)r1c * 128 + kc * 16;
        float2 f00 = *(const float2*)(Ar0 + 2 * tg);
        float2 f01 = *(const float2*)(Ar0 + 2 * tg + 8);
        float2 f10 = *(const float2*)(Ar1 + 2 * tg);
        float2 f11 = *(const float2*)(Ar1 + 2 * tg + 8);
        unsigned ah0, al0, ah1, al1, ah2, al2, ah3, al3;
        bsplit2(f00.x, f00.y, ah0, al0);
        bsplit2(f10.x, f10.y, ah1, al1);
        bsplit2(f01.x, f01.y, ah2, al2);
        bsplit2(f11.x, f11.y, ah3, al3);

        const uint4* wrow = sW + kc * 16 * 32 + lane;
        #pragma unroll
        for (int nc = 0; nc < 16; nc++) {
            uint4 w = wrow[nc * 32];
            MMA_BF16(acc[nc][0], acc[nc][1], acc[nc][2], acc[nc][3],
                     ah0, ah1, ah2, ah3, w.x, w.y);
            MMA_BF16(acc[nc][0], acc[nc][1], acc[nc][2], acc[nc][3],
                     ah0, ah1, ah2, ah3, w.z, w.w);
            MMA_BF16(acc[nc][0], acc[nc][1], acc[nc][2], acc[nc][3],
                     al0, al1, al2, al3, w.x, w.y);
        }
    }

    #pragma unroll
    for (int nc = 0; nc < 16; nc++) {
        int col = nc * 8 + 2 * tg;
        __half2 v0 = __floats2half2_rn(acc[nc][0], acc[nc][1]);
        __half2 v1 = __floats2half2_rn(acc[nc][2], acc[nc][3]);
        if (r0 < NN) *(__half2*)(g_hh + (size_t)r0 * 128 + col) = v0;
        if (r1 < NN) *(__half2*)(g_hh + (size_t)r1 * 128 + col) = v1;
    }
}

// ---------------- register-only fp16x4 -> float4 ----------------
__device__ __forceinline__ float4 h4tof4(uint2 u) {
    __half2_raw r0, r1;
    r0.x = (unsigned short)(u.x & 0xFFFFu);
    r0.y = (unsigned short)(u.x >> 16);
    r1.x = (unsigned short)(u.y & 0xFFFFu);
    r1.y = (unsigned short)(u.y >> 16);
    float2 f0 = __half22float2(__half2(r0));
    float2 f1 = __half22float2(__half2(r1));
    return make_float4(f0.x, f0.y, f1.x, f1.y);
}

// ---------------- aggregation: warp per node ----------------
__global__ void agg_kernel(const float* __restrict__ bias, int relu) {
    int gw = (blockIdx.x * blockDim.x + threadIdx.x) >> 5;
    int lane = threadIdx.x & 31;
    if (gw >= NN) return;
    const uint2* __restrict__ hh = (const uint2*)g_hh;
    float4 acc = ((const float4*)bias)[lane];
    float di = g_dinv[gw];
    float s = di * di;
    float4 hv = h4tof4(hh[gw * 32 + lane]);
    acc.x += s * hv.x; acc.y += s * hv.y; acc.z += s * hv.z; acc.w += s * hv.w;

    int e = g_rowptr[gw], ee = g_rowptr[gw + 1];
    for (; e + 4 <= ee; e += 4) {
        int2 ew0 = g_ew[e],     ew1 = g_ew[e + 1];
        int2 ew2 = g_ew[e + 2], ew3 = g_ew[e + 3];
        float w0 = __int_as_float(ew0.y), w1 = __int_as_float(ew1.y);
        float w2 = __int_as_float(ew2.y), w3 = __int_as_float(ew3.y);
        float4 v0 = h4tof4(hh[ew0.x * 32 + lane]);
        float4 v1 = h4tof4(hh[ew1.x * 32 + lane]);
        float4 v2 = h4tof4(hh[ew2.x * 32 + lane]);
        float4 v3 = h4tof4(hh[ew3.x * 32 + lane]);
        acc.x += w0 * v0.x; acc.y += w0 * v0.y; acc.z += w0 * v0.z; acc.w += w0 * v0.w;
        acc.x += w1 * v1.x; acc.y += w1 * v1.y; acc.z += w1 * v1.z; acc.w += w1 * v1.w;
        acc.x += w2 * v2.x; acc.y += w2 * v2.y; acc.z += w2 * v2.z; acc.w += w2 * v2.w;
        acc.x += w3 * v3.x; acc.y += w3 * v3.y; acc.z += w3 * v3.z; acc.w += w3 * v3.w;
    }
    for (; e < ee; e++) {
        int2 ew = g_ew[e];
        float w = __int_as_float(ew.y);
        float4 v = h4tof4(hh[ew.x * 32 + lane]);
        acc.x += w * v.x; acc.y += w * v.y; acc.z += w * v.z; acc.w += w * v.w;
    }
    if (relu) {
        acc.x = fmaxf(acc.x, 0.f); acc.y = fmaxf(acc.y, 0.f);
        acc.z = fmaxf(acc.z, 0.f); acc.w = fmaxf(acc.w, 0.f);
    }
    ((float4*)g_a)[gw * 32 + lane] = acc;
}

// ---------------- pool with inline suffix-min gfix ----------------
__global__ void poolfix_kernel(float* __restrict__ out) {
    __shared__ int s[NG + 1];
    int t = threadIdx.x;       // 128 threads
    s[t] = g_gstart[t];
    if (t == 0) s[NG] = g_gstart[NG];
    __syncthreads();
    #pragma unroll
    for (int off = 1; off <= NG; off <<= 1) {
        int v = NN;
        if (t + off <= NG) v = s[t + off];
        __syncthreads();
        s[t] = min(s[t], v);
        __syncthreads();
    }
    int g = blockIdx.x;
    int c = t;
    int sidx = s[g], eidx = s[g + 1];
    float acc = 0.f;
    int i = sidx;
    for (; i + 4 <= eidx; i += 4) {
        float t0 = g_a[i * 128 + c];
        float t1 = g_a[(i + 1) * 128 + c];
        float t2 = g_a[(i + 2) * 128 + c];
        float t3 = g_a[(i + 3) * 128 + c];
        acc += (t0 + t1) + (t2 + t3);
    }
    for (; i < eidx; i++) acc += g_a[i * 128 + c];
    out[g * 128 + c] = acc;
}

extern "C" void kernel_launch(void* const* d_in, const int* in_sizes, int n_in,
                              void* d_out, int out_size) {
    const float* x     = (const float*)d_in[0];
    const int*   ei    = (const int*)d_in[1];
    const int*   batch = (const int*)d_in[2];
    const float* W1    = (const float*)d_in[3];
    const float* b1    = (const float*)d_in[4];
    const float* W2    = (const float*)d_in[5];
    const float* b2    = (const float*)d_in[6];
    float* out = (float*)d_out;

    static cudaStream_t sB;
    static cudaEvent_t e0, e1;
    static bool initd = false;
    if (!initd) {
        cudaStreamCreateWithFlags(&sB, cudaStreamNonBlocking);
        cudaEventCreateWithFlags(&e0, cudaEventDisableTiming);
        cudaEventCreateWithFlags(&e1, cudaEventDisableTiming);
        cudaFuncSetAttribute(gemm_mma_kernel, cudaFuncAttributeMaxDynamicSharedMemorySize, 65536);
        initd = true;
    }

    // fork: side stream does pack + gemm1 (independent of graph prep)
    cudaEventRecord(e0, 0);
    cudaStreamWaitEvent(sB, e0, 0);
    pack_kernel<<<32, 256, 0, sB>>>(W1, W2);
    gemm_mma_kernel<<<(NN + 127) / 128, 256, 65536, sB>>>(x, 0, 0);
    cudaEventRecord(e1, sB);

    // main stream: graph prep
    init_kernel<<<(NN + 255) / 256, 256>>>();
    count_kernel<<<(NE + 255) / 256, 256>>>(ei);
    scanall_kernel<<<NSCANB, 256>>>(batch);
    fill_kernel<<<(NE + 255) / 256, 256>>>(ei);

    // join: agg1 needs both fill (main) and gemm1 (sB)
    cudaStreamWaitEvent(0, e1, 0);

    agg_kernel<<<(NN * 32 + 255) / 256, 256>>>(b1, 1);
    gemm_mma_kernel<<<(NN + 127) / 128, 256, 65536>>>(nullptr, 1, 1);
    agg_kernel<<<(NN * 32 + 255) / 256, 256>>>(b2, 0);
    poolfix_kernel<<<NG, 128>>>(out);
}